// round 1
// baseline (speedup 1.0000x reference)
#include <cuda_runtime.h>
#include <math.h>

#define K 32
#define INV_SQRT_2PI 0.3989422804014327f
// S = sqrt(0.5 * log2(e)) : arg of exp2 is -(S*z)^2
#define S_CONST 0.8493218002880191f

__device__ float4 g_tab[K * K];  // .x=isc (S/sigma), .y=mscn (-S*mu/sigma), .z=c21, .w=c10w

__device__ __forceinline__ float ex2f(float x) {
    float r;
    asm("ex2.approx.ftz.f32 %0, %1;" : "=f"(r) : "f"(x));
    return r;
}

// One block, 1024 threads. Computes softmaxes + folds all constants.
__global__ void prep_kernel(const float* __restrict__ Wk0,
                            const float* __restrict__ W10,
                            const float* __restrict__ W21,
                            const float* __restrict__ mu,
                            const float* __restrict__ sigma) {
    __shared__ float w0s[K];
    __shared__ float m10[K], s10[K], m21[K], s21[K];
    int tid = threadIdx.x;

    if (tid == 0) {
        float mx = -1e30f;
        for (int k = 0; k < K; k++) mx = fmaxf(mx, Wk0[k]);
        float s = 0.f;
        for (int k = 0; k < K; k++) s += expf(Wk0[k] - mx);
        float inv = 1.f / s;
        for (int k = 0; k < K; k++) w0s[k] = expf(Wk0[k] - mx) * inv;
    }
    if (tid < K) {  // column-softmax stats for W10, column b = tid
        int b = tid;
        float mx = -1e30f;
        for (int a = 0; a < K; a++) mx = fmaxf(mx, W10[a * K + b]);
        float s = 0.f;
        for (int a = 0; a < K; a++) s += expf(W10[a * K + b] - mx);
        m10[b] = mx; s10[b] = 1.f / s;
    } else if (tid < 2 * K) {  // W21 columns
        int b = tid - K;
        float mx = -1e30f;
        for (int a = 0; a < K; a++) mx = fmaxf(mx, W21[a * K + b]);
        float s = 0.f;
        for (int a = 0; a < K; a++) s += expf(W21[a * K + b] - mx);
        m21[b] = mx; s21[b] = 1.f / s;
    }
    __syncthreads();

    if (tid < K * K) {
        int b = tid % K;
        float sg = sigma[tid];
        float muv = mu[tid];
        float inv_sg = 1.f / sg;
        float w21v = expf(W21[tid] - m21[b]) * s21[b];
        float w10v = expf(W10[tid] - m10[b]) * s10[b];
        float4 t;
        t.x = S_CONST * inv_sg;
        t.y = -S_CONST * muv * inv_sg;
        t.z = w21v * INV_SQRT_2PI * inv_sg;
        t.w = w10v * w0s[b] * INV_SQRT_2PI * inv_sg;
        g_tab[tid] = t;
    }
}

__global__ void __launch_bounds__(128) tt_gauss_kernel(const float* __restrict__ X,
                                                       float* __restrict__ out,
                                                       int n) {
    __shared__ float4 tab[K * K];
    for (int i = threadIdx.x; i < K * K; i += blockDim.x) tab[i] = g_tab[i];
    __syncthreads();

    int idx = blockIdx.x * blockDim.x + threadIdx.x;
    if (idx >= n) return;

    float2 x = ((const float2*)X)[idx];  // x.x = X[n,0], x.y = X[n,1]

    float inner[K];
#pragma unroll
    for (int b = 0; b < K; b++) inner[b] = 0.f;

    // Stage 1: inner[b] = sum_a w21[a,b] * N(x1; mu[a,b], sigma[a,b])
#pragma unroll 1
    for (int a = 0; a < K; a++) {
        const float4* row = &tab[a * K];
#pragma unroll
        for (int b = 0; b < K; b++) {
            float4 t = row[b];
            float u = fmaf(x.y, t.x, t.y);
            float p = ex2f(-u * u);
            inner[b] = fmaf(t.z, p, inner[b]);
        }
    }

    // Stage 2: lik = sum_{a,b} w10[a,b]*w0[b] * N(x0; mu[a,b], sigma[a,b]) * inner[a]
    float lik = 0.f;
#pragma unroll 1
    for (int a = 0; a < K; a++) {
        float ia = inner[a];
        const float4* row = &tab[a * K];
#pragma unroll
        for (int b = 0; b < K; b++) {
            float4 t = row[b];
            float u = fmaf(x.x, t.x, t.y);
            float p = ex2f(-u * u);
            lik = fmaf(t.w * p, ia, lik);
        }
    }

    out[idx] = __logf(lik + 2.2204460492503131e-16f);
}

extern "C" void kernel_launch(void* const* d_in, const int* in_sizes, int n_in,
                              void* d_out, int out_size) {
    const float* X     = (const float*)d_in[0];
    const float* Wk0   = (const float*)d_in[1];
    const float* Wk1k0 = (const float*)d_in[2];
    const float* Wk2k1 = (const float*)d_in[3];
    const float* mu    = (const float*)d_in[4];
    const float* sigma = (const float*)d_in[5];
    float* out = (float*)d_out;
    int n = in_sizes[0] / 2;

    prep_kernel<<<1, 1024>>>(Wk0, Wk1k0, Wk2k1, mu, sigma);
    int threads = 128;
    int blocks = (n + threads - 1) / threads;
    tt_gauss_kernel<<<blocks, threads>>>(X, out, n);
}

// round 2
// speedup vs baseline: 2.6483x; 2.6483x over previous
#include <cuda_runtime.h>
#include <math.h>

#define K 32
#define G 4096
#define XMIN -8.0f
#define INV_H 256.0f          // G / 16
#define H_STEP 0.00390625f    // 16 / G
#define INV_SQRT_2PI 0.3989422804014327f
#define S_CONST 0.8493218002880191f   // sqrt(0.5*log2(e))
#define EPS 2.2204460492503131e-16f
#define NCHUNK 133            // ceil((G-1)/31)

__device__ float4 g_tab[K * K];   // .x=S/sigma .y=-S*mu/sigma .z=w21*C/sigma .w=w10*w0*C/sigma
__device__ float2 g_tabF[G * K];  // F_a(x_g): (value, next-value - value)
__device__ float2 g_tabI[G * K];  // I_a(x_g)

__device__ __forceinline__ float ex2f(float x) {
    float r;
    asm("ex2.approx.ftz.f32 %0, %1;" : "=f"(r) : "f"(x));
    return r;
}

// ---------------- prep: softmaxes + constant folding (1 block) ----------------
__global__ void prep_kernel(const float* __restrict__ Wk0,
                            const float* __restrict__ W10,
                            const float* __restrict__ W21,
                            const float* __restrict__ mu,
                            const float* __restrict__ sigma) {
    __shared__ float w0s[K];
    __shared__ float m10[K], s10[K], m21[K], s21[K];
    int tid = threadIdx.x;

    if (tid == 0) {
        float mx = -1e30f;
        for (int k = 0; k < K; k++) mx = fmaxf(mx, Wk0[k]);
        float s = 0.f;
        for (int k = 0; k < K; k++) s += expf(Wk0[k] - mx);
        float inv = 1.f / s;
        for (int k = 0; k < K; k++) w0s[k] = expf(Wk0[k] - mx) * inv;
    }
    if (tid < K) {
        int b = tid;
        float mx = -1e30f;
        for (int a = 0; a < K; a++) mx = fmaxf(mx, W10[a * K + b]);
        float s = 0.f;
        for (int a = 0; a < K; a++) s += expf(W10[a * K + b] - mx);
        m10[b] = mx; s10[b] = 1.f / s;
    } else if (tid < 2 * K) {
        int b = tid - K;
        float mx = -1e30f;
        for (int a = 0; a < K; a++) mx = fmaxf(mx, W21[a * K + b]);
        float s = 0.f;
        for (int a = 0; a < K; a++) s += expf(W21[a * K + b] - mx);
        m21[b] = mx; s21[b] = 1.f / s;
    }
    __syncthreads();

    if (tid < K * K) {
        int b = tid % K;
        float sg = sigma[tid];
        float inv_sg = 1.f / sg;
        float w21v = expf(W21[tid] - m21[b]) * s21[b];
        float w10v = expf(W10[tid] - m10[b]) * s10[b];
        float4 t;
        t.x = S_CONST * inv_sg;
        t.y = -S_CONST * mu[tid] * inv_sg;
        t.z = w21v * INV_SQRT_2PI * inv_sg;
        t.w = w10v * w0s[b] * INV_SQRT_2PI * inv_sg;
        g_tab[tid] = t;
    }
}

// ---------------- build the 64 1-D function tables ----------------
// grid: dim3(34, K, 2), block 128. Warp = one 31-wide (overlapping) g-chunk of one
// function; lane g computes v(x_g), slope via shfl from lane+1.
__global__ void build_kernel() {
    int lane = threadIdx.x & 31;
    int chunk = blockIdx.x * 4 + (threadIdx.x >> 5);
    if (chunk >= NCHUNK) return;
    int f = blockIdx.y;      // function index a
    int tsel = blockIdx.z;   // 0 -> F table, 1 -> I table

    int g = chunk * 31 + lane;
    if (g > G - 1) g = G - 1;
    float x = XMIN + g * H_STEP;

    float v = 0.f;
    if (tsel == 0) {
        // F_a(x) = sum_b tab[a,b].w * pdf(x; a,b)
#pragma unroll
        for (int j = 0; j < K; j++) {
            float4 c = g_tab[f * K + j];
            float u = fmaf(x, c.x, c.y);
            v = fmaf(c.w, ex2f(-u * u), v);
        }
    } else {
        // I_a(x) = sum_c tab[c,a].z * pdf(x; c,a)
#pragma unroll
        for (int i = 0; i < K; i++) {
            float4 c = g_tab[i * K + f];
            float u = fmaf(x, c.x, c.y);
            v = fmaf(c.z, ex2f(-u * u), v);
        }
    }

    float vn = __shfl_down_sync(0xffffffffu, v, 1);
    if (lane < 31 && g < G - 1) {
        float2 e;
        e.x = v;
        e.y = vn - v;
        if (tsel == 0) g_tabF[g * K + f] = e;
        else           g_tabI[g * K + f] = e;
    }
}

// ---------------- main: warp-cooperative interpolation + dot ----------------
__global__ void __launch_bounds__(128) tt_main(const float* __restrict__ X,
                                               float* __restrict__ out, int n) {
    __shared__ float4 sp[4][32];          // per-warp sample params
    __shared__ float prodm[4][32][33];    // [warp][sample][component], padded

    int lane = threadIdx.x & 31;
    int w = threadIdx.x >> 5;
    int sidx = (blockIdx.x * 4 + w) * 32 + lane;

    float2 x = make_float2(0.f, 0.f);
    if (sidx < n) x = ((const float2*)X)[sidx];

    float t0 = (x.x - XMIN) * INV_H;
    float t1 = (x.y - XMIN) * INV_H;
    float g0f = fminf(fmaxf(floorf(t0), 0.f), (float)(G - 2));
    float g1f = fminf(fmaxf(floorf(t1), 0.f), (float)(G - 2));
    sp[w][lane] = make_float4(g0f, t0 - g0f, g1f, t1 - g1f);
    __syncwarp();

#pragma unroll 8
    for (int s = 0; s < 32; s++) {
        float4 p = sp[w][s];
        int g0 = (int)p.x;
        int g1 = (int)p.z;
        float2 fF = g_tabF[g0 * K + lane];   // coalesced: 256B contiguous per warp
        float2 fI = g_tabI[g1 * K + lane];
        float vF = fmaf(p.y, fF.y, fF.x);
        float vI = fmaf(p.w, fI.y, fI.x);
        prodm[w][s][lane] = vF * vI;
    }
    __syncwarp();

    float acc = 0.f;
#pragma unroll
    for (int i = 0; i < 32; i++) acc += prodm[w][lane][i];

    if (sidx < n) out[sidx] = __logf(acc + EPS);
}

extern "C" void kernel_launch(void* const* d_in, const int* in_sizes, int n_in,
                              void* d_out, int out_size) {
    const float* X     = (const float*)d_in[0];
    const float* Wk0   = (const float*)d_in[1];
    const float* Wk1k0 = (const float*)d_in[2];
    const float* Wk2k1 = (const float*)d_in[3];
    const float* mu    = (const float*)d_in[4];
    const float* sigma = (const float*)d_in[5];
    float* out = (float*)d_out;
    int n = in_sizes[0] / 2;

    prep_kernel<<<1, 1024>>>(Wk0, Wk1k0, Wk2k1, mu, sigma);
    build_kernel<<<dim3(34, K, 2), 128>>>();
    int blocks = (n + 127) / 128;
    tt_main<<<blocks, 128>>>(X, out, n);
}

// round 3
// speedup vs baseline: 3.2208x; 1.2162x over previous
#include <cuda_runtime.h>
#include <math.h>

#define K 32
#define G 1024
#define XMIN -6.5f
#define RANGE 13.0f
#define INV_H (G / RANGE)            // 78.769231
#define H_STEP (RANGE / G)           // 0.0126953125
#define INV_SQRT_2PI 0.3989422804014327f
#define S_CONST 0.8493218002880191f  // sqrt(0.5*log2(e))
#define EPS 2.2204460492503131e-16f
#define NCHUNK 33                    // ceil((G-1)/31)

__device__ float4 g_tab[K * K];
__device__ float2 g_tabF[G * K];
__device__ float2 g_tabI[G * K];

__device__ __forceinline__ float ex2f(float x) {
    float r;
    asm("ex2.approx.ftz.f32 %0, %1;" : "=f"(r) : "f"(x));
    return r;
}

// ---------------- prep: fully parallel softmaxes (1 block, 1024 thr) ----------------
// warp j owns column j; lane i = row i. Column softmax = warp shfl reduction.
__global__ void prep_kernel(const float* __restrict__ Wk0,
                            const float* __restrict__ W10,
                            const float* __restrict__ W21,
                            const float* __restrict__ mu,
                            const float* __restrict__ sigma) {
    __shared__ float w0s[K];
    int lane = threadIdx.x & 31;  // row i
    int j = threadIdx.x >> 5;     // col j

    if (j == 0) {
        float v = Wk0[lane];
        float mx = v;
#pragma unroll
        for (int o = 16; o; o >>= 1) mx = fmaxf(mx, __shfl_xor_sync(~0u, mx, o));
        float e = __expf(v - mx);
        float s = e;
#pragma unroll
        for (int o = 16; o; o >>= 1) s += __shfl_xor_sync(~0u, s, o);
        w0s[lane] = e / s;
    }
    __syncthreads();

    int idx = lane * K + j;  // element (i=lane, j)
    float v10 = W10[idx];
    float v21 = W21[idx];

    float mx10 = v10, mx21 = v21;
#pragma unroll
    for (int o = 16; o; o >>= 1) {
        mx10 = fmaxf(mx10, __shfl_xor_sync(~0u, mx10, o));
        mx21 = fmaxf(mx21, __shfl_xor_sync(~0u, mx21, o));
    }
    float e10 = __expf(v10 - mx10);
    float e21 = __expf(v21 - mx21);
    float s10 = e10, s21 = e21;
#pragma unroll
    for (int o = 16; o; o >>= 1) {
        s10 += __shfl_xor_sync(~0u, s10, o);
        s21 += __shfl_xor_sync(~0u, s21, o);
    }
    float w10v = e10 / s10;
    float w21v = e21 / s21;

    float sg = sigma[idx];
    float inv_sg = 1.f / sg;
    float4 t;
    t.x = S_CONST * inv_sg;
    t.y = -S_CONST * mu[idx] * inv_sg;
    t.z = w21v * INV_SQRT_2PI * inv_sg;
    t.w = w10v * w0s[j] * INV_SQRT_2PI * inv_sg;
    g_tab[idx] = t;
}

// ---------------- build the 64 1-D function tables ----------------
// grid: dim3(9, K, 2), block 128. Warp = one 31-wide overlapping g-chunk.
__global__ void build_kernel() {
    int lane = threadIdx.x & 31;
    int chunk = blockIdx.x * 4 + (threadIdx.x >> 5);
    if (chunk >= NCHUNK) return;
    int f = blockIdx.y;
    int tsel = blockIdx.z;

    int g = chunk * 31 + lane;
    if (g > G - 1) g = G - 1;
    float x = XMIN + g * H_STEP;

    float v = 0.f;
    if (tsel == 0) {
#pragma unroll
        for (int j = 0; j < K; j++) {
            float4 c = g_tab[f * K + j];
            float u = fmaf(x, c.x, c.y);
            v = fmaf(c.w, ex2f(-u * u), v);
        }
    } else {
#pragma unroll
        for (int i = 0; i < K; i++) {
            float4 c = g_tab[i * K + f];
            float u = fmaf(x, c.x, c.y);
            v = fmaf(c.z, ex2f(-u * u), v);
        }
    }

    float vn = __shfl_down_sync(0xffffffffu, v, 1);
    if (lane < 31 && g < G - 1) {
        float2 e;
        e.x = v;
        e.y = vn - v;
        if (tsel == 0) g_tabF[g * K + f] = e;
        else           g_tabI[g * K + f] = e;
    }
}

// ---------------- main: warp-cooperative interpolation + dot ----------------
__global__ void __launch_bounds__(128) tt_main(const float* __restrict__ X,
                                               float* __restrict__ out, int n) {
    __shared__ float4 sp[4][32];
    __shared__ float prodm[4][32][33];

    int lane = threadIdx.x & 31;
    int w = threadIdx.x >> 5;
    int sidx = (blockIdx.x * 4 + w) * 32 + lane;

    float2 x = make_float2(0.f, 0.f);
    if (sidx < n) x = ((const float2*)X)[sidx];

    float t0 = (x.x - XMIN) * INV_H;
    float t1 = (x.y - XMIN) * INV_H;
    float g0f = fminf(fmaxf(floorf(t0), 0.f), (float)(G - 2));
    float g1f = fminf(fmaxf(floorf(t1), 0.f), (float)(G - 2));
    sp[w][lane] = make_float4(g0f, t0 - g0f, g1f, t1 - g1f);
    __syncwarp();

#pragma unroll 8
    for (int s = 0; s < 32; s++) {
        float4 p = sp[w][s];
        int g0 = (int)p.x;
        int g1 = (int)p.z;
        float2 fF = __ldg(&g_tabF[g0 * K + lane]);  // 256B contiguous per warp
        float2 fI = __ldg(&g_tabI[g1 * K + lane]);
        float vF = fmaf(p.y, fF.y, fF.x);
        float vI = fmaf(p.w, fI.y, fI.x);
        prodm[w][s][lane] = vF * vI;
    }
    __syncwarp();

    float acc = 0.f;
#pragma unroll
    for (int i = 0; i < 32; i++) acc += prodm[w][lane][i];

    if (sidx < n) out[sidx] = __logf(acc + EPS);
}

extern "C" void kernel_launch(void* const* d_in, const int* in_sizes, int n_in,
                              void* d_out, int out_size) {
    const float* X     = (const float*)d_in[0];
    const float* Wk0   = (const float*)d_in[1];
    const float* Wk1k0 = (const float*)d_in[2];
    const float* Wk2k1 = (const float*)d_in[3];
    const float* mu    = (const float*)d_in[4];
    const float* sigma = (const float*)d_in[5];
    float* out = (float*)d_out;
    int n = in_sizes[0] / 2;

    prep_kernel<<<1, 1024>>>(Wk0, Wk1k0, Wk2k1, mu, sigma);
    build_kernel<<<dim3(9, K, 2), 128>>>();
    int blocks = (n + 127) / 128;
    tt_main<<<blocks, 128>>>(X, out, n);
}

// round 5
// speedup vs baseline: 3.9298x; 1.2201x over previous
#include <cuda_runtime.h>
#include <math.h>

#define K 32
#define G 1024
#define XMIN -6.5f
#define RANGE 13.0f
#define INV_H (G / RANGE)
#define H_STEP (RANGE / G)
#define INV_SQRT_2PI 0.3989422804014327f
#define S_CONST 0.8493218002880191f  // sqrt(0.5*log2(e))
#define EPS 2.2204460492503131e-16f
#define NCHUNK 33                    // 33*31 = 1023 = G-1

__device__ float2 g_tabF[G * K];
__device__ float2 g_tabI[G * K];

__device__ __forceinline__ float ex2f(float x) {
    float r;
    asm("ex2.approx.ftz.f32 %0, %1;" : "=f"(r) : "f"(x));
    return r;
}

// ---------------- fused prep + build ----------------
// grid dim3(NCHUNK, 2), 256 threads. Every block redundantly computes the
// softmax-folded coefficient table into smem, then builds its 31-wide slice
// of all 32 functions of one table (F or I).
__global__ void __launch_bounds__(256) build_kernel(const float* __restrict__ Wk0,
                                                    const float* __restrict__ W10,
                                                    const float* __restrict__ W21,
                                                    const float* __restrict__ mu,
                                                    const float* __restrict__ sigma) {
    __shared__ float4 s_tab[K * K];  // .x=S/sig .y=-S*mu/sig .z=w21*C/sig .w=w10*w0*C/sig
    __shared__ float w0s[K];

    int lane = threadIdx.x & 31;   // row i
    int w = threadIdx.x >> 5;      // warp 0..7

    // w0 softmax (warp 0)
    if (w == 0) {
        float v = Wk0[lane];
        float mx = v;
#pragma unroll
        for (int o = 16; o; o >>= 1) mx = fmaxf(mx, __shfl_xor_sync(~0u, mx, o));
        float e = __expf(v - mx);
        float s = e;
#pragma unroll
        for (int o = 16; o; o >>= 1) s += __shfl_xor_sync(~0u, s, o);
        w0s[lane] = e / s;
    }

    // column softmaxes: warp w owns columns w, w+8, w+16, w+24
    float w10v[4], w21v[4];
    float sgv[4], muv[4];
    int cols[4];
#pragma unroll
    for (int c = 0; c < 4; c++) {
        int j = w + c * 8;
        cols[c] = j;
        int idx = lane * K + j;
        float v10 = W10[idx];
        float v21 = W21[idx];
        sgv[c] = sigma[idx];
        muv[c] = mu[idx];
        float mx10 = v10, mx21 = v21;
#pragma unroll
        for (int o = 16; o; o >>= 1) {
            mx10 = fmaxf(mx10, __shfl_xor_sync(~0u, mx10, o));
            mx21 = fmaxf(mx21, __shfl_xor_sync(~0u, mx21, o));
        }
        float e10 = __expf(v10 - mx10);
        float e21 = __expf(v21 - mx21);
        float s10 = e10, s21 = e21;
#pragma unroll
        for (int o = 16; o; o >>= 1) {
            s10 += __shfl_xor_sync(~0u, s10, o);
            s21 += __shfl_xor_sync(~0u, s21, o);
        }
        w10v[c] = e10 / s10;
        w21v[c] = e21 / s21;
    }
    __syncthreads();  // w0s ready

#pragma unroll
    for (int c = 0; c < 4; c++) {
        int j = cols[c];
        float inv_sg = 1.f / sgv[c];
        float4 t;
        t.x = S_CONST * inv_sg;
        t.y = -S_CONST * muv[c] * inv_sg;
        t.z = w21v[c] * INV_SQRT_2PI * inv_sg;
        t.w = w10v[c] * w0s[j] * INV_SQRT_2PI * inv_sg;
        s_tab[lane * K + j] = t;
    }
    __syncthreads();  // s_tab ready

    // build: chunk = blockIdx.x, tsel = blockIdx.y; lane = grid point
    int chunk = blockIdx.x;
    int tsel = blockIdx.y;
    int g = chunk * 31 + lane;
    if (g > G - 1) g = G - 1;
    float x = XMIN + g * H_STEP;

#pragma unroll
    for (int c = 0; c < 4; c++) {
        int f = w + c * 8;
        float v = 0.f;
        if (tsel == 0) {
            // F_f(x) = sum_b s_tab[f,b].w * pdf(x; f,b)
#pragma unroll
            for (int j = 0; j < K; j++) {
                float4 t = s_tab[f * K + j];
                float u = fmaf(x, t.x, t.y);
                v = fmaf(t.w, ex2f(-u * u), v);
            }
        } else {
            // I_f(x) = sum_i s_tab[i,f].z * pdf(x; i,f)
#pragma unroll
            for (int i = 0; i < K; i++) {
                float4 t = s_tab[i * K + f];
                float u = fmaf(x, t.x, t.y);
                v = fmaf(t.z, ex2f(-u * u), v);
            }
        }
        float vn = __shfl_down_sync(0xffffffffu, v, 1);
        if (lane < 31 && g < G - 1) {
            float2 e;
            e.x = v;
            e.y = vn - v;
            if (tsel == 0) g_tabF[g * K + f] = e;
            else           g_tabI[g * K + f] = e;
        }
    }
}

// ---------------- main: 2 samples / warp-iter, LDG.128 ----------------
__global__ void __launch_bounds__(128) tt_main(const float* __restrict__ X,
                                               float* __restrict__ out, int n) {
    __shared__ float4 sp[4][32];
    __shared__ float prodm[4][32][17];

    int lane = threadIdx.x & 31;
    int w = threadIdx.x >> 5;
    int sidx = (blockIdx.x * 4 + w) * 32 + lane;

    float2 x = make_float2(0.f, 0.f);
    if (sidx < n) x = ((const float2*)X)[sidx];

    float t0 = (x.x - XMIN) * INV_H;
    float t1 = (x.y - XMIN) * INV_H;
    float g0f = fminf(fmaxf(floorf(t0), 0.f), (float)(G - 2));
    float g1f = fminf(fmaxf(floorf(t1), 0.f), (float)(G - 2));
    sp[w][lane] = make_float4(g0f, t0 - g0f, g1f, t1 - g1f);
    __syncwarp();

    int half = lane >> 4;     // lanes 0-15 -> sample s, 16-31 -> sample s+1
    int pair = lane & 15;     // component pair index (covers comps 2p, 2p+1)

#pragma unroll
    for (int s = 0; s < 32; s += 2) {
        float4 p = sp[w][s + half];
        int g0 = (int)p.x;
        int g1 = (int)p.z;
        float4 fF = *(const float4*)&g_tabF[g0 * K + pair * 2];
        float4 fI = *(const float4*)&g_tabI[g1 * K + pair * 2];
        float vF0 = fmaf(p.y, fF.y, fF.x);
        float vF1 = fmaf(p.y, fF.w, fF.z);
        float vI0 = fmaf(p.w, fI.y, fI.x);
        float vI1 = fmaf(p.w, fI.w, fI.z);
        prodm[w][s + half][pair] = vF0 * vI0 + vF1 * vI1;
    }
    __syncwarp();

    float acc = 0.f;
#pragma unroll
    for (int i = 0; i < 16; i++) acc += prodm[w][lane][i];

    if (sidx < n) out[sidx] = __logf(acc + EPS);
}

extern "C" void kernel_launch(void* const* d_in, const int* in_sizes, int n_in,
                              void* d_out, int out_size) {
    const float* X     = (const float*)d_in[0];
    const float* Wk0   = (const float*)d_in[1];
    const float* Wk1k0 = (const float*)d_in[2];
    const float* Wk2k1 = (const float*)d_in[3];
    const float* mu    = (const float*)d_in[4];
    const float* sigma = (const float*)d_in[5];
    float* out = (float*)d_out;
    int n = in_sizes[0] / 2;

    build_kernel<<<dim3(NCHUNK, 2), 256>>>(Wk0, Wk1k0, Wk2k1, mu, sigma);
    int blocks = (n + 127) / 128;
    tt_main<<<blocks, 128>>>(X, out, n);
}

// round 6
// speedup vs baseline: 4.4634x; 1.1358x over previous
#include <cuda_runtime.h>
#include <math.h>

#define K 32
#define G 1024
#define XMIN -6.5f
#define RANGE 13.0f
#define INV_H (G / RANGE)
#define H_STEP (RANGE / G)
#define INV_SQRT_2PI 0.3989422804014327f
#define S_CONST 0.8493218002880191f  // sqrt(0.5*log2(e))
#define EPS 2.2204460492503131e-16f
#define NCHUNK 33                    // 33*31 = 1023 = G-1

__device__ float2 g_tabF[G * K];
__device__ float2 g_tabI[G * K];

__device__ __forceinline__ float ex2f(float x) {
    float r;
    asm("ex2.approx.ftz.f32 %0, %1;" : "=f"(r) : "f"(x));
    return r;
}

// ---------------- fused prep + build ----------------
// grid dim3(NCHUNK, 2), 512 threads (16 warps). Each block redundantly folds the
// softmax coefficient table into smem, then builds its 31-wide slice of all 32
// functions of one table (F or I). Warp w owns columns/functions {w, w+16}.
__global__ void __launch_bounds__(512) build_kernel(const float* __restrict__ Wk0,
                                                    const float* __restrict__ W10,
                                                    const float* __restrict__ W21,
                                                    const float* __restrict__ mu,
                                                    const float* __restrict__ sigma) {
    __shared__ float4 s_tab[K * K];
    __shared__ float w0s[K];

    int lane = threadIdx.x & 31;   // row i
    int w = threadIdx.x >> 5;      // warp 0..15

    if (w == 0) {
        float v = Wk0[lane];
        float mx = v;
#pragma unroll
        for (int o = 16; o; o >>= 1) mx = fmaxf(mx, __shfl_xor_sync(~0u, mx, o));
        float e = __expf(v - mx);
        float s = e;
#pragma unroll
        for (int o = 16; o; o >>= 1) s += __shfl_xor_sync(~0u, s, o);
        w0s[lane] = e / s;
    }

    float w10v[2], w21v[2], sgv[2], muv[2];
#pragma unroll
    for (int c = 0; c < 2; c++) {
        int j = w + c * 16;
        int idx = lane * K + j;
        float v10 = W10[idx];
        float v21 = W21[idx];
        sgv[c] = sigma[idx];
        muv[c] = mu[idx];
        float mx10 = v10, mx21 = v21;
#pragma unroll
        for (int o = 16; o; o >>= 1) {
            mx10 = fmaxf(mx10, __shfl_xor_sync(~0u, mx10, o));
            mx21 = fmaxf(mx21, __shfl_xor_sync(~0u, mx21, o));
        }
        float e10 = __expf(v10 - mx10);
        float e21 = __expf(v21 - mx21);
        float s10 = e10, s21 = e21;
#pragma unroll
        for (int o = 16; o; o >>= 1) {
            s10 += __shfl_xor_sync(~0u, s10, o);
            s21 += __shfl_xor_sync(~0u, s21, o);
        }
        w10v[c] = e10 / s10;
        w21v[c] = e21 / s21;
    }
    __syncthreads();  // w0s ready

#pragma unroll
    for (int c = 0; c < 2; c++) {
        int j = w + c * 16;
        float inv_sg = 1.f / sgv[c];
        float4 t;
        t.x = S_CONST * inv_sg;
        t.y = -S_CONST * muv[c] * inv_sg;
        t.z = w21v[c] * INV_SQRT_2PI * inv_sg;
        t.w = w10v[c] * w0s[j] * INV_SQRT_2PI * inv_sg;
        s_tab[lane * K + j] = t;
    }
    __syncthreads();  // s_tab ready

    int chunk = blockIdx.x;
    int tsel = blockIdx.y;
    int g = chunk * 31 + lane;
    if (g > G - 1) g = G - 1;
    float x = XMIN + g * H_STEP;

#pragma unroll
    for (int c = 0; c < 2; c++) {
        int f = w + c * 16;
        float v = 0.f;
        if (tsel == 0) {
#pragma unroll
            for (int j = 0; j < K; j++) {
                float4 t = s_tab[f * K + j];
                float u = fmaf(x, t.x, t.y);
                v = fmaf(t.w, ex2f(-u * u), v);
            }
        } else {
#pragma unroll
            for (int i = 0; i < K; i++) {
                float4 t = s_tab[i * K + f];
                float u = fmaf(x, t.x, t.y);
                v = fmaf(t.z, ex2f(-u * u), v);
            }
        }
        float vn = __shfl_down_sync(0xffffffffu, v, 1);
        if (lane < 31 && g < G - 1) {
            float2 e;
            e.x = v;
            e.y = vn - v;
            if (tsel == 0) g_tabF[g * K + f] = e;
            else           g_tabI[g * K + f] = e;
        }
    }
}

// ---------------- main: explicit MLP batching, LDG.128 ----------------
__global__ void __launch_bounds__(128, 4) tt_main(const float* __restrict__ X,
                                                  float* __restrict__ out, int n) {
    __shared__ float4 sp[4][32];
    __shared__ float prodm[4][32][17];

    int lane = threadIdx.x & 31;
    int w = threadIdx.x >> 5;
    int sidx = (blockIdx.x * 4 + w) * 32 + lane;

    float2 x = make_float2(0.f, 0.f);
    if (sidx < n) x = ((const float2*)X)[sidx];

    float t0 = (x.x - XMIN) * INV_H;
    float t1 = (x.y - XMIN) * INV_H;
    float g0f = fminf(fmaxf(floorf(t0), 0.f), (float)(G - 2));
    float g1f = fminf(fmaxf(floorf(t1), 0.f), (float)(G - 2));
    sp[w][lane] = make_float4(g0f, t0 - g0f, g1f, t1 - g1f);
    __syncwarp();

    int half = lane >> 4;   // lanes 0-15 -> even sample, 16-31 -> odd sample
    int pair = lane & 15;   // component pair: covers comps 2p, 2p+1

#pragma unroll
    for (int b = 0; b < 2; b++) {
        int base = b * 16;
        float4 pv[8];
#pragma unroll
        for (int t = 0; t < 8; t++) pv[t] = sp[w][base + 2 * t + half];

        float4 dF[8], dI[8];
#pragma unroll
        for (int t = 0; t < 8; t++) {
            dF[t] = *(const float4*)&g_tabF[((int)pv[t].x) * K + pair * 2];
            dI[t] = *(const float4*)&g_tabI[((int)pv[t].z) * K + pair * 2];
        }

#pragma unroll
        for (int t = 0; t < 8; t++) {
            float vF0 = fmaf(pv[t].y, dF[t].y, dF[t].x);
            float vF1 = fmaf(pv[t].y, dF[t].w, dF[t].z);
            float vI0 = fmaf(pv[t].w, dI[t].y, dI[t].x);
            float vI1 = fmaf(pv[t].w, dI[t].w, dI[t].z);
            prodm[w][base + 2 * t + half][pair] = vF0 * vI0 + vF1 * vI1;
        }
    }
    __syncwarp();

    float acc = 0.f;
#pragma unroll
    for (int i = 0; i < 16; i++) acc += prodm[w][lane][i];

    if (sidx < n) out[sidx] = __logf(acc + EPS);
}

extern "C" void kernel_launch(void* const* d_in, const int* in_sizes, int n_in,
                              void* d_out, int out_size) {
    const float* X     = (const float*)d_in[0];
    const float* Wk0   = (const float*)d_in[1];
    const float* Wk1k0 = (const float*)d_in[2];
    const float* Wk2k1 = (const float*)d_in[3];
    const float* mu    = (const float*)d_in[4];
    const float* sigma = (const float*)d_in[5];
    float* out = (float*)d_out;
    int n = in_sizes[0] / 2;

    build_kernel<<<dim3(NCHUNK, 2), 512>>>(Wk0, Wk1k0, Wk2k1, mu, sigma);
    int blocks = (n + 127) / 128;
    tt_main<<<blocks, 128>>>(X, out, n);
}